// round 3
// baseline (speedup 1.0000x reference)
#include <cuda_runtime.h>

// Ragged segment mean:
//   seq:   [B=2048, L=512, D=512] fp32   (d_in[0])
//   begin: [B] int32                      (d_in[1])
//   end:   [B] int32                      (d_in[2])
//   out:   [B, D] fp32 = mean(seq[b, begin[b]:end[b], :], axis=0)
//
// One CTA per batch row. 128 threads x float4 = 512 floats = one full D-row
// per iteration, perfectly coalesced. Unroll x4 over L for MLP.

#define B_DIM 2048
#define L_DIM 512
#define D_DIM 512
#define THREADS 128          // D_DIM / 4

__global__ __launch_bounds__(THREADS)
void ragged_mean_kernel(const float* __restrict__ seq,
                        const int* __restrict__ begin,
                        const int* __restrict__ end,
                        float* __restrict__ out) {
    const int b = blockIdx.x;
    const int t = threadIdx.x;  // 0..127, owns columns [4t, 4t+4)

    const int s = begin[b];
    const int e = end[b];

    // float4 view of this batch row; row stride in float4 units = D/4 = 128
    const float4* base =
        reinterpret_cast<const float4*>(seq + (size_t)b * L_DIM * D_DIM) + t;

    float ax = 0.f, ay = 0.f, az = 0.f, aw = 0.f;

    int l = s;
    // Main loop: 4 independent LDG.128 per thread per iteration (MLP >= 4)
    for (; l + 4 <= e; l += 4) {
        float4 v0 = base[(size_t)(l + 0) * (D_DIM / 4)];
        float4 v1 = base[(size_t)(l + 1) * (D_DIM / 4)];
        float4 v2 = base[(size_t)(l + 2) * (D_DIM / 4)];
        float4 v3 = base[(size_t)(l + 3) * (D_DIM / 4)];
        ax += v0.x + v1.x + v2.x + v3.x;
        ay += v0.y + v1.y + v2.y + v3.y;
        az += v0.z + v1.z + v2.z + v3.z;
        aw += v0.w + v1.w + v2.w + v3.w;
    }
    // Tail (0..3 rows)
    for (; l < e; ++l) {
        float4 v = base[(size_t)l * (D_DIM / 4)];
        ax += v.x; ay += v.y; az += v.z; aw += v.w;
    }

    const float inv = 1.0f / (float)(e - s);
    float4 r;
    r.x = ax * inv; r.y = ay * inv; r.z = az * inv; r.w = aw * inv;

    reinterpret_cast<float4*>(out + (size_t)b * D_DIM)[t] = r;
}

extern "C" void kernel_launch(void* const* d_in, const int* in_sizes, int n_in,
                              void* d_out, int out_size) {
    const float* seq   = (const float*)d_in[0];
    const int*   begin = (const int*)d_in[1];
    const int*   end   = (const int*)d_in[2];
    float*       out   = (float*)d_out;

    ragged_mean_kernel<<<B_DIM, THREADS>>>(seq, begin, end, out);
}

// round 4
// speedup vs baseline: 1.0028x; 1.0028x over previous
#include <cuda_runtime.h>

// Ragged segment mean:
//   seq:   [B=2048, L=512, D=512] fp32   (d_in[0])
//   begin: [B] int32                      (d_in[1])
//   end:   [B] int32                      (d_in[2])
//   out:   [B, D] fp32 = mean(seq[b, begin[b]:end[b], :], axis=0)
//
// One CTA per batch row. 128 threads x float4 = 512 floats = one full D-row
// per iteration, perfectly coalesced. Unroll x4 over L for MLP.

#define B_DIM 2048
#define L_DIM 512
#define D_DIM 512
#define THREADS 128          // D_DIM / 4

__global__ __launch_bounds__(THREADS)
void ragged_mean_kernel(const float* __restrict__ seq,
                        const int* __restrict__ begin,
                        const int* __restrict__ end,
                        float* __restrict__ out) {
    const int b = blockIdx.x;
    const int t = threadIdx.x;  // 0..127, owns columns [4t, 4t+4)

    const int s = begin[b];
    const int e = end[b];

    // float4 view of this batch row; row stride in float4 units = D/4 = 128
    const float4* base =
        reinterpret_cast<const float4*>(seq + (size_t)b * L_DIM * D_DIM) + t;

    float ax = 0.f, ay = 0.f, az = 0.f, aw = 0.f;

    int l = s;
    // Main loop: 4 independent LDG.128 per thread per iteration (MLP >= 4)
    for (; l + 4 <= e; l += 4) {
        float4 v0 = base[(size_t)(l + 0) * (D_DIM / 4)];
        float4 v1 = base[(size_t)(l + 1) * (D_DIM / 4)];
        float4 v2 = base[(size_t)(l + 2) * (D_DIM / 4)];
        float4 v3 = base[(size_t)(l + 3) * (D_DIM / 4)];
        ax += v0.x + v1.x + v2.x + v3.x;
        ay += v0.y + v1.y + v2.y + v3.y;
        az += v0.z + v1.z + v2.z + v3.z;
        aw += v0.w + v1.w + v2.w + v3.w;
    }
    // Tail (0..3 rows)
    for (; l < e; ++l) {
        float4 v = base[(size_t)l * (D_DIM / 4)];
        ax += v.x; ay += v.y; az += v.z; aw += v.w;
    }

    const float inv = 1.0f / (float)(e - s);
    float4 r;
    r.x = ax * inv; r.y = ay * inv; r.z = az * inv; r.w = aw * inv;

    reinterpret_cast<float4*>(out + (size_t)b * D_DIM)[t] = r;
}

extern "C" void kernel_launch(void* const* d_in, const int* in_sizes, int n_in,
                              void* d_out, int out_size) {
    const float* seq   = (const float*)d_in[0];
    const int*   begin = (const int*)d_in[1];
    const int*   end   = (const int*)d_in[2];
    float*       out   = (float*)d_out;

    ragged_mean_kernel<<<B_DIM, THREADS>>>(seq, begin, end, out);
}

// round 5
// speedup vs baseline: 1.0774x; 1.0743x over previous
#include <cuda_runtime.h>

// Ragged segment mean, L-chunked for load balance:
//   seq:   [B=2048, L=512, D=512] fp32   (d_in[0])
//   begin: [B] int32                      (d_in[1])
//   end:   [B] int32                      (d_in[2])
//   out:   [B, D] fp32 = mean(seq[b, begin[b]:end[b], :], axis=0)
//
// Kernel 1 zeroes out. Kernel 2: grid (B, L/CHUNK); each CTA sums the
// intersection of its 64-row chunk with [begin,end), scales by 1/count,
// and REDG-adds into out. 16384 CTAs -> many waves -> work-stealing
// removes the ragged-length imbalance that capped R3 at 75% DRAM.

#define B_DIM   2048
#define L_DIM   512
#define D_DIM   512
#define THREADS 128          // D_DIM / 4 lanes of float4
#define CHUNK   64
#define NCHUNK  (L_DIM / CHUNK)   // 8

__global__ __launch_bounds__(THREADS)
void zero_out_kernel(float4* __restrict__ out) {
    // 2048 blocks x 128 threads x 1 float4 = 2048*512 floats
    out[(size_t)blockIdx.x * THREADS + threadIdx.x] =
        make_float4(0.f, 0.f, 0.f, 0.f);
}

__global__ __launch_bounds__(THREADS)
void ragged_mean_chunk_kernel(const float* __restrict__ seq,
                              const int* __restrict__ begin,
                              const int* __restrict__ end,
                              float* __restrict__ out) {
    const int b = blockIdx.x;
    const int c = blockIdx.y;
    const int t = threadIdx.x;  // owns columns [4t, 4t+4)

    const int sb = begin[b];
    const int eb = end[b];

    // Intersection of this chunk with [sb, eb)
    int s = c * CHUNK;       if (sb > s) s = sb;
    int e = (c + 1) * CHUNK; if (eb < e) e = eb;
    if (s >= e) return;

    const float4* base =
        reinterpret_cast<const float4*>(seq + (size_t)b * L_DIM * D_DIM) + t;

    float ax = 0.f, ay = 0.f, az = 0.f, aw = 0.f;

    int l = s;
    for (; l + 4 <= e; l += 4) {
        float4 v0 = __ldcs(&base[(size_t)(l + 0) * (D_DIM / 4)]);
        float4 v1 = __ldcs(&base[(size_t)(l + 1) * (D_DIM / 4)]);
        float4 v2 = __ldcs(&base[(size_t)(l + 2) * (D_DIM / 4)]);
        float4 v3 = __ldcs(&base[(size_t)(l + 3) * (D_DIM / 4)]);
        ax += v0.x + v1.x + v2.x + v3.x;
        ay += v0.y + v1.y + v2.y + v3.y;
        az += v0.z + v1.z + v2.z + v3.z;
        aw += v0.w + v1.w + v2.w + v3.w;
    }
    for (; l < e; ++l) {
        float4 v = __ldcs(&base[(size_t)l * (D_DIM / 4)]);
        ax += v.x; ay += v.y; az += v.z; aw += v.w;
    }

    const float inv = 1.0f / (float)(eb - sb);
    float* dst = out + (size_t)b * D_DIM + 4 * t;
    atomicAdd(dst + 0, ax * inv);   // REDG.ADD (return unused)
    atomicAdd(dst + 1, ay * inv);
    atomicAdd(dst + 2, az * inv);
    atomicAdd(dst + 3, aw * inv);
}

extern "C" void kernel_launch(void* const* d_in, const int* in_sizes, int n_in,
                              void* d_out, int out_size) {
    const float* seq   = (const float*)d_in[0];
    const int*   begin = (const int*)d_in[1];
    const int*   end   = (const int*)d_in[2];
    float*       out   = (float*)d_out;

    zero_out_kernel<<<B_DIM, THREADS>>>((float4*)out);

    dim3 grid(B_DIM, NCHUNK);
    ragged_mean_chunk_kernel<<<grid, THREADS>>>(seq, begin, end, out);
}